// round 7
// baseline (speedup 1.0000x reference)
#include <cuda_runtime.h>
#include <cuda_bf16.h>

// HungarianMatcher cost matrix, diagonal only.
//   out[b,q,t] = |cq-ct|+|wq-wt| - softmax(logits[b,q])[label_t] - gIoU(scaled)
// MUFU-bound kernel: 3/4 of exps on MUFU (__expf), 1/4 on the FMA pipe via a
// polynomial exp, to break the MUFU throughput ceiling measured in round 3.

#define BS 64
#define NQ 300
#define NC 200
#define NT 32
#define WARPS_PER_BLOCK 8
#define NC4 (NC / 4)   // 50 float4 per row

// FMA-pipe exp: exp(x) = 2^(x*log2e). Magic-number split into integer n and
// fraction f in [-0.5, 0.5], degree-5 polynomial for 2^f, exponent inserted
// by integer add on the bit pattern. Rel err ~2e-6; valid for |x| < ~60
// (logits are N(0,1), so |x| < ~6 in practice).
__device__ __forceinline__ float exp_fma(float x)
{
    float z = x * 1.4426950408889634f;            // x * log2(e)
    float t = z + 12582912.0f;                    // 1.5*2^23: n in low mantissa
    int   i = __float_as_int(t);                  // low bits == n (mod 2^23)
    float f = z - (t - 12582912.0f);              // f = z - round(z)
    float p =             1.3333558146e-3f;       // ~ln2^5/120
    p = fmaf(p, f, 9.6181291076e-3f);             // ~ln2^4/24
    p = fmaf(p, f, 5.5504108665e-2f);             // ~ln2^3/6
    p = fmaf(p, f, 2.4022650696e-1f);             // ~ln2^2/2
    p = fmaf(p, f, 6.9314718056e-1f);             // ~ln2
    p = fmaf(p, f, 1.0f);
    return __int_as_float(__float_as_int(p) + (i << 23));
}

__global__ __launch_bounds__(WARPS_PER_BLOCK * 32)
void matcher_kernel(const float* __restrict__ logits,
                    const float* __restrict__ pred_seg,
                    const float* __restrict__ tgt_seg,
                    const float* __restrict__ lengths,
                    const int*   __restrict__ labels32,
                    float* __restrict__ out)
{
    const int b    = blockIdx.y;
    const int warp = threadIdx.x >> 5;
    const int lane = threadIdx.x & 31;
    const int q    = blockIdx.x * WARPS_PER_BLOCK + warp;

    __shared__ __align__(16) float s_exp[WARPS_PER_BLOCK][NC];
    __shared__ float s_tc[NT], s_tw[NT];   // target center/width (unscaled)
    __shared__ float s_ts[NT], s_te[NT];   // target start/end (scaled by L)
    __shared__ int   s_lab[NT];

    const float L = lengths[b];

    // First 32 threads load targets; probe batch-0 labels for dtype
    // (JAX int64 usually demotes to int32; detect at runtime to be robust).
    if (threadIdx.x < NT) {
        const int t  = threadIdx.x;
        const int lo = labels32[2 * t];
        const int hi = labels32[2 * t + 1];
        const bool ok64 = (hi == 0) && ((unsigned)lo < (unsigned)NC);
        const unsigned m = __ballot_sync(0xffffffffu, ok64);
        const bool is64 = (m == 0xffffffffu);

        const int idx = b * NT + t;
        s_lab[t] = is64 ? labels32[2 * idx] : labels32[idx];

        const float c = tgt_seg[(size_t)idx * 2 + 0];
        const float w = tgt_seg[(size_t)idx * 2 + 1];
        s_tc[t] = c;
        s_tw[t] = w;
        const float cs = c * L;
        const float ws = w * L;
        s_ts[t] = cs - 0.5f * ws;
        s_te[t] = cs + 0.5f * ws;
    }
    __syncthreads();

    if (q >= NQ) return;

    // ---- softmax denominator (one warp per row, float4 loads) ----
    const float4* __restrict__ row4 =
        (const float4*)(logits + ((size_t)b * NQ + q) * NC);
    float4* __restrict__ s_exp4 = (float4*)s_exp[warp];

    float sum = 0.0f;
    #pragma unroll
    for (int v = lane; v < NC4; v += 32) {
        const float4 f = row4[v];
        float4 e;
        e.x = __expf(f.x);        // MUFU
        e.y = __expf(f.y);        // MUFU
        e.z = __expf(f.z);        // MUFU
        e.w = exp_fma(f.w);       // FMA pipe — offloads 25% of MUFU work
        s_exp4[v] = e;
        sum += (e.x + e.y) + (e.z + e.w);
    }
    #pragma unroll
    for (int off = 16; off; off >>= 1)
        sum += __shfl_xor_sync(0xffffffffu, sum, off);
    const float inv_sum = 1.0f / sum;

    __syncwarp();  // s_exp visible across the warp before the label gather

    // ---- this query's segment ----
    const float cq = pred_seg[((size_t)b * NQ + q) * 2 + 0];
    const float wq = pred_seg[((size_t)b * NQ + q) * 2 + 1];
    const float cqs = cq * L;
    const float wqs = wq * L;
    const float s1 = cqs - 0.5f * wqs;
    const float e1 = cqs + 0.5f * wqs;
    const float len1 = e1 - s1;

    // ---- lane t handles target t (NT == 32) ----
    const int t = lane;
    const float cost_class = -s_exp[warp][s_lab[t]] * inv_sum;

    const float cost_seg = fabsf(cq - s_tc[t]) + fabsf(wq - s_tw[t]);

    const float s2 = s_ts[t];
    const float e2 = s_te[t];
    float inter = fminf(e1, e2) - fmaxf(s1, s2);
    inter = fmaxf(inter, 0.0f);
    const float uni = len1 + (e2 - s2) - inter;
    const float iou = inter / uni;
    const float enc = fmaxf(e1, e2) - fminf(s1, s2);
    const float giou = iou - (enc - uni) / enc;

    out[((size_t)b * NQ + q) * NT + t] = cost_seg + cost_class - giou;
}

extern "C" void kernel_launch(void* const* d_in, const int* in_sizes, int n_in,
                              void* d_out, int out_size)
{
    const float* logits   = (const float*)d_in[0];
    const float* pred_seg = (const float*)d_in[1];
    const float* tgt_seg  = (const float*)d_in[2];
    const float* lengths  = (const float*)d_in[3];
    const int*   labels   = (const int*)d_in[4];
    float*       out      = (float*)d_out;

    dim3 grid((NQ + WARPS_PER_BLOCK - 1) / WARPS_PER_BLOCK, BS);
    dim3 block(WARPS_PER_BLOCK * 32);
    matcher_kernel<<<grid, block>>>(logits, pred_seg, tgt_seg, lengths,
                                    labels, out);
}